// round 1
// baseline (speedup 1.0000x reference)
#include <cuda_runtime.h>
#include <cuda_bf16.h>
#include <math.h>

#define Bq 64
#define Tq 188
#define Vq 32000
#define BETA 2.0f

__device__ double g_acc;

__global__ void zero_kernel() {
    if (threadIdx.x == 0) g_acc = 0.0;
}

__global__ __launch_bounds__(256) void loss_kernel(
    const float* __restrict__ scores,   // [B, T, V]
    const int*   __restrict__ targets,  // [B, T]
    const int*   __restrict__ lengths)  // [B]
{
    const int bt = blockIdx.x;
    const int b = bt / Tq;
    const int t = bt - b * Tq;
    if (t >= lengths[b]) return;   // masked row: contributes 0, skip the read entirely

    const float* __restrict__ row = scores + (size_t)bt * Vq;
    const float4* __restrict__ row4 = (const float4*)row;

    // per-thread argmax with first-index tie-break (indices visited in increasing order)
    float vmax = -1e30f;
    int   imax = Vq;
    for (int i = threadIdx.x; i < Vq / 4; i += blockDim.x) {
        float4 v = row4[i];
        int base = i * 4;
        if (v.x > vmax) { vmax = v.x; imax = base;     }
        if (v.y > vmax) { vmax = v.y; imax = base + 1; }
        if (v.z > vmax) { vmax = v.z; imax = base + 2; }
        if (v.w > vmax) { vmax = v.w; imax = base + 3; }
    }

    // warp reduce: max value, ties -> smaller index (argmax-first semantics)
    #pragma unroll
    for (int off = 16; off; off >>= 1) {
        float ov = __shfl_down_sync(0xFFFFFFFFu, vmax, off);
        int   oi = __shfl_down_sync(0xFFFFFFFFu, imax, off);
        if (ov > vmax || (ov == vmax && oi < imax)) { vmax = ov; imax = oi; }
    }

    __shared__ float sv[8];
    __shared__ int   si[8];
    const int wid = threadIdx.x >> 5;
    const int lid = threadIdx.x & 31;
    if (lid == 0) { sv[wid] = vmax; si[wid] = imax; }
    __syncthreads();

    if (threadIdx.x == 0) {
        float fv = sv[0]; int fi = si[0];
        #pragma unroll
        for (int w = 1; w < 8; w++) {
            float ov = sv[w]; int oi = si[w];
            if (ov > fv || (ov == fv && oi < fi)) { fv = ov; fi = oi; }
        }
        const int target = targets[bt];
        const float gathered = __ldg(row + target);   // L2-hot: row was just streamed
        const float w = (fi == target && target != 0) ? BETA : 1.0f;
        atomicAdd(&g_acc, (double)(-w * logf(gathered)));
    }
}

__global__ void finalize_kernel(float* __restrict__ out) {
    if (threadIdx.x == 0) out[0] = (float)(g_acc / (double)Bq);
}

extern "C" void kernel_launch(void* const* d_in, const int* in_sizes, int n_in,
                              void* d_out, int out_size) {
    const float* scores  = (const float*)d_in[0];
    const int*   targets = (const int*)  d_in[1];
    const int*   lengths = (const int*)  d_in[2];
    float*       out     = (float*)d_out;

    zero_kernel<<<1, 32>>>();
    loss_kernel<<<Bq * Tq, 256>>>(scores, targets, lengths);
    finalize_kernel<<<1, 32>>>(out);
}